// round 2
// baseline (speedup 1.0000x reference)
#include <cuda_runtime.h>
#include <cuda_bf16.h>

#define NODE_D 128
#define NMAX   50048
#define EMAX   600064

// Scratch (device globals: no allocations allowed)
__device__ float g_h[2][NMAX * NODE_D];   // projected features
__device__ float g_s[2][NMAX];            // h . a_src
__device__ float g_t[2][NMAX];            // h . a_dst
__device__ float g_m[2][NMAX];            // segment max
__device__ float g_den[2][NMAX];          // segment sum of exp
__device__ int   g_ei[2][2 * EMAX];       // int32 edge indices (converted)
__device__ int   g_is64[2];               // dtype probe result

__device__ __forceinline__ float leaky(float x) { return x > 0.f ? x : 0.2f * x; }

// ---------------------------------------------------------------------------
// 0a) Probe: is the edge buffer int64 or int32?
//     int64 data: high 32-bit word of every entry is 0 (ids < 50000).
//     int32 data: "high words" are real node ids; all-zero is ~impossible.
// ---------------------------------------------------------------------------
__global__ void probe_kernel(const unsigned int* __restrict__ buf, int g) {
    int nz = 0;
#pragma unroll
    for (int i = 0; i < 32; i++) nz += (buf[2 * i + 1] != 0u);
    g_is64[g] = (nz == 0) ? 1 : 0;
}

// 0b) Convert edge indices to int32 scratch.
__global__ void convert_kernel(const void* __restrict__ buf, int n2e, int g) {
    int i = blockIdx.x * blockDim.x + threadIdx.x;
    if (i >= n2e) return;
    if (g_is64[g]) g_ei[g][i] = (int)((const long long*)buf)[i];
    else           g_ei[g][i] = ((const int*)buf)[i];
}

// ---------------------------------------------------------------------------
// 1) GEMM: h = x @ W   ([N,128] x [128,128])
// ---------------------------------------------------------------------------
__global__ void gemm_kernel(const float* __restrict__ x, const float* __restrict__ W,
                            int g, int N) {
    __shared__ float xs[8][64];
    __shared__ float ws[8][128];
    float* __restrict__ h = g_h[g];

    int tid = threadIdx.x;            // 0..255
    int ty = tid >> 5;                // 0..7  -> 8-row group
    int tx = tid & 31;                // 0..31 -> 4-col group
    int row0 = blockIdx.x * 64;

    float acc[8][4];
#pragma unroll
    for (int i = 0; i < 8; i++)
#pragma unroll
        for (int j = 0; j < 4; j++) acc[i][j] = 0.f;

    for (int k0 = 0; k0 < NODE_D; k0 += 8) {
#pragma unroll
        for (int i = 0; i < 2; i++) {
            int idx = tid + i * 256;      // 0..511
            int r = idx >> 3, k = idx & 7;
            int gr = row0 + r;
            xs[k][r] = (gr < N) ? x[gr * NODE_D + k0 + k] : 0.f;
        }
#pragma unroll
        for (int i = 0; i < 4; i++) {
            int idx = tid + i * 256;
            int k = idx >> 7, c = idx & 127;
            ws[k][c] = W[(k0 + k) * NODE_D + c];
        }
        __syncthreads();
#pragma unroll
        for (int k = 0; k < 8; k++) {
            float wv[4];
#pragma unroll
            for (int j = 0; j < 4; j++) wv[j] = ws[k][tx * 4 + j];
#pragma unroll
            for (int i = 0; i < 8; i++) {
                float xv = xs[k][ty * 8 + i];
#pragma unroll
                for (int j = 0; j < 4; j++) acc[i][j] = fmaf(xv, wv[j], acc[i][j]);
            }
        }
        __syncthreads();
    }
#pragma unroll
    for (int i = 0; i < 8; i++) {
        int gr = row0 + ty * 8 + i;
        if (gr < N) {
#pragma unroll
            for (int j = 0; j < 4; j++) h[gr * NODE_D + tx * 4 + j] = acc[i][j];
        }
    }
}

// ---------------------------------------------------------------------------
// 2) Per-node dots: s = h.a_src, t = h.a_dst, m = leaky(s+t) (self loop init)
// ---------------------------------------------------------------------------
__global__ void node_dots_kernel(const float* __restrict__ a_src,
                                 const float* __restrict__ a_dst,
                                 int g, int N) {
    int warp = (blockIdx.x * blockDim.x + threadIdx.x) >> 5;
    int lane = threadIdx.x & 31;
    if (warp >= N) return;
    const float4* hv = (const float4*)(g_h[g] + (size_t)warp * NODE_D);
    float4 a = ((const float4*)a_src)[lane];
    float4 b = ((const float4*)a_dst)[lane];
    float4 hh = hv[lane];
    float ss = hh.x * a.x + hh.y * a.y + hh.z * a.z + hh.w * a.w;
    float tt = hh.x * b.x + hh.y * b.y + hh.z * b.z + hh.w * b.w;
#pragma unroll
    for (int o = 16; o > 0; o >>= 1) {
        ss += __shfl_xor_sync(0xffffffffu, ss, o);
        tt += __shfl_xor_sync(0xffffffffu, tt, o);
    }
    if (lane == 0) {
        g_s[g][warp] = ss;
        g_t[g][warp] = tt;
        g_m[g][warp] = leaky(ss + tt);
    }
}

// ---------------------------------------------------------------------------
// 3) Edge max: atomic float-max of leaky(s[src]+t[dst]) into m[dst]
// ---------------------------------------------------------------------------
__global__ void edge_max_kernel(int E, int g) {
    int e = blockIdx.x * blockDim.x + threadIdx.x;
    if (e >= E) return;
    int src = g_ei[g][e];
    int dst = g_ei[g][E + e];
    float v = leaky(g_s[g][src] + g_t[g][dst]);
    float* mp = g_m[g] + dst;
    if (v >= 0.f) atomicMax((int*)mp, __float_as_int(v));
    else          atomicMin((unsigned int*)mp, __float_as_uint(v));
}

// ---------------------------------------------------------------------------
// 4) Per-node init: denom = exp(self - m), out = that * h[n]
// ---------------------------------------------------------------------------
__global__ void node_init_kernel(float* __restrict__ out, int g, int N) {
    int n = blockIdx.x;
    int j = threadIdx.x;
    float ex = __expf(leaky(g_s[g][n] + g_t[g][n]) - g_m[g][n]);
    if (j == 0) g_den[g][n] = ex;
    out[(size_t)n * NODE_D + j] = ex * g_h[g][(size_t)n * NODE_D + j];
}

// ---------------------------------------------------------------------------
// 5) Edge accumulate: one warp per edge.
// ---------------------------------------------------------------------------
__global__ void edge_acc_kernel(int E, int g, float* __restrict__ out) {
    int gw = (blockIdx.x * blockDim.x + threadIdx.x) >> 5;
    int lane = threadIdx.x & 31;
    if (gw >= E) return;
    int src = g_ei[g][gw];
    int dst = g_ei[g][E + gw];
    float ex = __expf(leaky(g_s[g][src] + g_t[g][dst]) - g_m[g][dst]);
    if (lane == 0) atomicAdd(g_den[g] + dst, ex);
    float4 hv = ((const float4*)(g_h[g] + (size_t)src * NODE_D))[lane];
    float* p = out + (size_t)dst * NODE_D + lane * 4;
    asm volatile("red.global.add.v4.f32 [%0], {%1, %2, %3, %4};"
                 :: "l"(p), "f"(ex * hv.x), "f"(ex * hv.y),
                    "f"(ex * hv.z), "f"(ex * hv.w)
                 : "memory");
}

// ---------------------------------------------------------------------------
// 6) Finalize: out = relu(out/(denom+eps) + bias)
// ---------------------------------------------------------------------------
__global__ void finalize_kernel(float* __restrict__ out, const float* __restrict__ bias,
                                int g, int N) {
    int n = blockIdx.x;
    int j = threadIdx.x;
    size_t idx = (size_t)n * NODE_D + j;
    float v = out[idx] / (g_den[g][n] + 1e-16f) + bias[j];
    out[idx] = fmaxf(v, 0.f);
}

// ---------------------------------------------------------------------------
extern "C" void kernel_launch(void* const* d_in, const int* in_sizes, int n_in,
                              void* d_out, int out_size) {
    const float* x1  = (const float*)d_in[0];
    const void*  ei1 = d_in[1];
    const float* x2  = (const float*)d_in[3];
    const void*  ei2 = d_in[4];
    const float* W1  = (const float*)d_in[6];
    const float* as1 = (const float*)d_in[7];
    const float* ad1 = (const float*)d_in[8];
    const float* b1  = (const float*)d_in[9];
    const float* W2  = (const float*)d_in[10];
    const float* as2 = (const float*)d_in[11];
    const float* ad2 = (const float*)d_in[12];
    const float* b2  = (const float*)d_in[13];

    int N = in_sizes[0] / NODE_D;
    int E = in_sizes[1] / 2;

    float* out1 = (float*)d_out;
    float* out2 = out1 + (size_t)N * NODE_D;

    int gemm_blocks = (N + 63) / 64;
    int dot_blocks  = (N + 7) / 8;          // 8 warps / block
    int emax_blocks = (E + 255) / 256;
    int eacc_blocks = (E + 7) / 8;          // 8 warps / block
    int conv_blocks = (2 * E + 255) / 256;

    // ---- graph 0 ----
    probe_kernel<<<1, 1>>>((const unsigned int*)ei1, 0);
    convert_kernel<<<conv_blocks, 256>>>(ei1, 2 * E, 0);
    gemm_kernel<<<gemm_blocks, 256>>>(x1, W1, 0, N);
    node_dots_kernel<<<dot_blocks, 256>>>(as1, ad1, 0, N);
    edge_max_kernel<<<emax_blocks, 256>>>(E, 0);
    node_init_kernel<<<N, 128>>>(out1, 0, N);
    edge_acc_kernel<<<eacc_blocks, 256>>>(E, 0, out1);
    finalize_kernel<<<N, 128>>>(out1, b1, 0, N);

    // ---- graph 1 ----
    probe_kernel<<<1, 1>>>((const unsigned int*)ei2, 1);
    convert_kernel<<<conv_blocks, 256>>>(ei2, 2 * E, 1);
    gemm_kernel<<<gemm_blocks, 256>>>(x2, W2, 1, N);
    node_dots_kernel<<<dot_blocks, 256>>>(as2, ad2, 1, N);
    edge_max_kernel<<<emax_blocks, 256>>>(E, 1);
    node_init_kernel<<<N, 128>>>(out2, 1, N);
    edge_acc_kernel<<<eacc_blocks, 256>>>(E, 1, out2);
    finalize_kernel<<<N, 128>>>(out2, b2, 1, N);
}

// round 3
// speedup vs baseline: 1.0249x; 1.0249x over previous
#include <cuda_runtime.h>
#include <cuda_bf16.h>

#define NODE_D 128
#define NMAX   50048
#define EMAX   600064

// Scratch (device globals: no allocations allowed)
__device__ float g_h[2][NMAX * NODE_D];   // projected features
__device__ float g_s[2][NMAX];            // h . a_src
__device__ float g_t[2][NMAX];            // h . a_dst
__device__ float g_m[2][NMAX];            // segment max
__device__ float g_den[2][NMAX];          // segment sum of exp
__device__ int   g_ei[2][2 * EMAX];       // int32 edge indices (converted)
__device__ int   g_is64[2];               // dtype probe result

__device__ __forceinline__ float leaky(float x) { return x > 0.f ? x : 0.2f * x; }

// ---------------------------------------------------------------------------
// 0a) Probe both edge buffers: int64 (all hi-words zero) vs int32.
// ---------------------------------------------------------------------------
__global__ void probe_kernel(const unsigned int* __restrict__ b0,
                             const unsigned int* __restrict__ b1) {
    int g = threadIdx.x;
    if (g >= 2) return;
    const unsigned int* buf = g ? b1 : b0;
    int nz = 0;
#pragma unroll
    for (int i = 0; i < 32; i++) nz += (buf[2 * i + 1] != 0u);
    g_is64[g] = (nz == 0) ? 1 : 0;
}

// 0b) Convert edge indices to int32 scratch (both graphs, grid.y = 2).
__global__ void convert_kernel(const void* __restrict__ b0,
                               const void* __restrict__ b1, int n2e) {
    int g = blockIdx.y;
    const void* buf = g ? b1 : b0;
    int i = blockIdx.x * blockDim.x + threadIdx.x;
    if (i >= n2e) return;
    if (g_is64[g]) g_ei[g][i] = (int)((const long long*)buf)[i];
    else           g_ei[g][i] = ((const int*)buf)[i];
}

// ---------------------------------------------------------------------------
// 1) GEMM: h = x @ W. BM=128, BN=128 (full), BK=16, 256 threads, 8x8 microtile.
// ---------------------------------------------------------------------------
__global__ __launch_bounds__(256, 2)
void gemm_kernel(const float* __restrict__ x0, const float* __restrict__ W0,
                 const float* __restrict__ x1, const float* __restrict__ W1,
                 int N) {
    int g = blockIdx.y;
    const float* __restrict__ x = g ? x1 : x0;
    const float* __restrict__ W = g ? W1 : W0;
    float* __restrict__ h = g_h[g];

    __shared__ float xs[16][129];   // [k][row], padded
    __shared__ float ws[16][128];   // [k][col]

    int tid = threadIdx.x;            // 0..255
    int tx = tid & 15;                // col group (8 cols)
    int ty = tid >> 4;                // row group (8 rows)
    int row0 = blockIdx.x * 128;

    float acc[8][8];
#pragma unroll
    for (int i = 0; i < 8; i++)
#pragma unroll
        for (int j = 0; j < 8; j++) acc[i][j] = 0.f;

    for (int k0 = 0; k0 < NODE_D; k0 += 16) {
        // x tile: 128 rows x 16 k = 512 float4 (2 per thread), transposed store
#pragma unroll
        for (int i = 0; i < 2; i++) {
            int idx = tid + i * 256;          // 0..511
            int r = idx >> 2, kq = idx & 3;   // row, k-quad
            int gr = row0 + r;
            float4 v = (gr < N) ? ((const float4*)x)[gr * (NODE_D / 4) + (k0 >> 2) + kq]
                                : make_float4(0.f, 0.f, 0.f, 0.f);
            xs[kq * 4 + 0][r] = v.x;
            xs[kq * 4 + 1][r] = v.y;
            xs[kq * 4 + 2][r] = v.z;
            xs[kq * 4 + 3][r] = v.w;
        }
        // W tile: 16 k x 128 cols = 512 float4 (2 per thread)
#pragma unroll
        for (int i = 0; i < 2; i++) {
            int idx = tid + i * 256;
            int k = idx >> 5, c4 = idx & 31;
            ((float4*)ws[k])[c4] = ((const float4*)W)[(k0 + k) * (NODE_D / 4) + c4];
        }
        __syncthreads();
#pragma unroll
        for (int k = 0; k < 16; k++) {
            float xv[8], wv[8];
#pragma unroll
            for (int i = 0; i < 8; i++) xv[i] = xs[k][ty * 8 + i];
            float4 w0 = ((const float4*)ws[k])[tx * 2];
            float4 w1 = ((const float4*)ws[k])[tx * 2 + 1];
            wv[0] = w0.x; wv[1] = w0.y; wv[2] = w0.z; wv[3] = w0.w;
            wv[4] = w1.x; wv[5] = w1.y; wv[6] = w1.z; wv[7] = w1.w;
#pragma unroll
            for (int i = 0; i < 8; i++)
#pragma unroll
                for (int j = 0; j < 8; j++)
                    acc[i][j] = fmaf(xv[i], wv[j], acc[i][j]);
        }
        __syncthreads();
    }
#pragma unroll
    for (int i = 0; i < 8; i++) {
        int gr = row0 + ty * 8 + i;
        if (gr < N) {
            float4 o0 = make_float4(acc[i][0], acc[i][1], acc[i][2], acc[i][3]);
            float4 o1 = make_float4(acc[i][4], acc[i][5], acc[i][6], acc[i][7]);
            ((float4*)h)[gr * (NODE_D / 4) + tx * 2]     = o0;
            ((float4*)h)[gr * (NODE_D / 4) + tx * 2 + 1] = o1;
        }
    }
}

// ---------------------------------------------------------------------------
// 2) Per-node dots: s = h.a_src, t = h.a_dst, m = leaky(s+t) (self loop init)
// ---------------------------------------------------------------------------
__global__ void node_dots_kernel(const float* __restrict__ as0, const float* __restrict__ ad0,
                                 const float* __restrict__ as1, const float* __restrict__ ad1,
                                 int N) {
    int g = blockIdx.y;
    const float* a_src = g ? as1 : as0;
    const float* a_dst = g ? ad1 : ad0;
    int warp = (blockIdx.x * blockDim.x + threadIdx.x) >> 5;
    int lane = threadIdx.x & 31;
    if (warp >= N) return;
    const float4* hv = (const float4*)(g_h[g] + (size_t)warp * NODE_D);
    float4 a = ((const float4*)a_src)[lane];
    float4 b = ((const float4*)a_dst)[lane];
    float4 hh = hv[lane];
    float ss = hh.x * a.x + hh.y * a.y + hh.z * a.z + hh.w * a.w;
    float tt = hh.x * b.x + hh.y * b.y + hh.z * b.z + hh.w * b.w;
#pragma unroll
    for (int o = 16; o > 0; o >>= 1) {
        ss += __shfl_xor_sync(0xffffffffu, ss, o);
        tt += __shfl_xor_sync(0xffffffffu, tt, o);
    }
    if (lane == 0) {
        g_s[g][warp] = ss;
        g_t[g][warp] = tt;
        g_m[g][warp] = leaky(ss + tt);
    }
}

// ---------------------------------------------------------------------------
// 3) Edge max: atomic float-max of leaky(s[src]+t[dst]) into m[dst]
// ---------------------------------------------------------------------------
__global__ void edge_max_kernel(int E) {
    int g = blockIdx.y;
    int e = blockIdx.x * blockDim.x + threadIdx.x;
    if (e >= E) return;
    int src = g_ei[g][e];
    int dst = g_ei[g][E + e];
    float v = leaky(g_s[g][src] + g_t[g][dst]);
    float* mp = g_m[g] + dst;
    if (v >= 0.f) atomicMax((int*)mp, __float_as_int(v));
    else          atomicMin((unsigned int*)mp, __float_as_uint(v));
}

// ---------------------------------------------------------------------------
// 4) Per-node init: denom = exp(self - m), out = that * h[n]
// ---------------------------------------------------------------------------
__global__ void node_init_kernel(float* __restrict__ out_base, int N) {
    int g = blockIdx.y;
    int n = blockIdx.x;
    int j = threadIdx.x;
    float* out = out_base + (size_t)g * N * NODE_D;
    float ex = __expf(leaky(g_s[g][n] + g_t[g][n]) - g_m[g][n]);
    if (j == 0) g_den[g][n] = ex;
    out[(size_t)n * NODE_D + j] = ex * g_h[g][(size_t)n * NODE_D + j];
}

// ---------------------------------------------------------------------------
// 5) Edge accumulate: one warp per edge.
// ---------------------------------------------------------------------------
__global__ void edge_acc_kernel(int E, int N, float* __restrict__ out_base) {
    int g = blockIdx.y;
    int gw = (blockIdx.x * blockDim.x + threadIdx.x) >> 5;
    int lane = threadIdx.x & 31;
    if (gw >= E) return;
    float* out = out_base + (size_t)g * N * NODE_D;
    int src = g_ei[g][gw];
    int dst = g_ei[g][E + gw];
    float ex = __expf(leaky(g_s[g][src] + g_t[g][dst]) - g_m[g][dst]);
    if (lane == 0) atomicAdd(g_den[g] + dst, ex);
    float4 hv = ((const float4*)(g_h[g] + (size_t)src * NODE_D))[lane];
    float* p = out + (size_t)dst * NODE_D + lane * 4;
    asm volatile("red.global.add.v4.f32 [%0], {%1, %2, %3, %4};"
                 :: "l"(p), "f"(ex * hv.x), "f"(ex * hv.y),
                    "f"(ex * hv.z), "f"(ex * hv.w)
                 : "memory");
}

// ---------------------------------------------------------------------------
// 6) Finalize: out = relu(out/(denom+eps) + bias)
// ---------------------------------------------------------------------------
__global__ void finalize_kernel(float* __restrict__ out_base,
                                const float* __restrict__ bias0,
                                const float* __restrict__ bias1, int N) {
    int g = blockIdx.y;
    int n = blockIdx.x;
    int j = threadIdx.x;
    const float* bias = g ? bias1 : bias0;
    float* out = out_base + (size_t)g * N * NODE_D;
    size_t idx = (size_t)n * NODE_D + j;
    float v = out[idx] / (g_den[g][n] + 1e-16f) + bias[j];
    out[idx] = fmaxf(v, 0.f);
}

// ---------------------------------------------------------------------------
extern "C" void kernel_launch(void* const* d_in, const int* in_sizes, int n_in,
                              void* d_out, int out_size) {
    const float* x1  = (const float*)d_in[0];
    const void*  ei1 = d_in[1];
    const float* x2  = (const float*)d_in[3];
    const void*  ei2 = d_in[4];
    const float* W1  = (const float*)d_in[6];
    const float* as1 = (const float*)d_in[7];
    const float* ad1 = (const float*)d_in[8];
    const float* b1  = (const float*)d_in[9];
    const float* W2  = (const float*)d_in[10];
    const float* as2 = (const float*)d_in[11];
    const float* ad2 = (const float*)d_in[12];
    const float* b2  = (const float*)d_in[13];

    int N = in_sizes[0] / NODE_D;
    int E = in_sizes[1] / 2;

    float* out = (float*)d_out;

    dim3 conv_grid((2 * E + 255) / 256, 2);
    dim3 gemm_grid((N + 127) / 128, 2);
    dim3 dot_grid((N + 7) / 8, 2);          // 8 warps / block
    dim3 emax_grid((E + 255) / 256, 2);
    dim3 node_grid(N, 2);
    dim3 eacc_grid((E + 7) / 8, 2);         // 8 warps / block

    probe_kernel<<<1, 2>>>((const unsigned int*)ei1, (const unsigned int*)ei2);
    convert_kernel<<<conv_grid, 256>>>(ei1, ei2, 2 * E);
    gemm_kernel<<<gemm_grid, 256>>>(x1, W1, x2, W2, N);
    node_dots_kernel<<<dot_grid, 256>>>(as1, ad1, as2, ad2, N);
    edge_max_kernel<<<emax_grid, 256>>>(E);
    node_init_kernel<<<node_grid, 128>>>(out, N);
    edge_acc_kernel<<<eacc_grid, 256>>>(E, N, out);
    finalize_kernel<<<node_grid, 128>>>(out, b1, b2, N);
}

// round 4
// speedup vs baseline: 2.1085x; 2.0572x over previous
#include <cuda_runtime.h>
#include <cuda_bf16.h>

#define NODE_D 128
#define NMAX   50048
#define EMAX   600064
#define SCAN_B 1024

// Scratch (device globals: no allocations allowed)
__device__ float g_h[2][NMAX * NODE_D];   // projected features
__device__ float g_s[2][NMAX];            // h . a_src
__device__ float g_t[2][NMAX];            // h . a_dst
__device__ int   g_deg[2][NMAX];          // in-degree (excl self loop)
__device__ int   g_start[2][NMAX];        // CSR row start
__device__ int   g_cursor[2][NMAX];       // scatter cursor
__device__ int   g_csr[2][EMAX];          // src ids grouped by dst
__device__ int   g_ei[2][2 * EMAX];       // int32 edge indices (converted)
__device__ int   g_is64[2];               // dtype probe result
__device__ int   g_bsum[2][64];           // scan block sums

__device__ __forceinline__ float leaky(float x) { return x > 0.f ? x : 0.2f * x; }

// ---------------------------------------------------------------------------
// 0a) Probe both edge buffers: int64 (all hi-words zero) vs int32.
// ---------------------------------------------------------------------------
__global__ void probe_kernel(const unsigned int* __restrict__ b0,
                             const unsigned int* __restrict__ b1) {
    int g = threadIdx.x;
    if (g >= 2) return;
    const unsigned int* buf = g ? b1 : b0;
    int nz = 0;
#pragma unroll
    for (int i = 0; i < 32; i++) nz += (buf[2 * i + 1] != 0u);
    g_is64[g] = (nz == 0) ? 1 : 0;
}

// 0b) Zero degree counters (graph replays need this every call).
__global__ void zero_deg_kernel(int N) {
    int g = blockIdx.y;
    int i = blockIdx.x * blockDim.x + threadIdx.x;
    if (i < N) g_deg[g][i] = 0;
}

// 0c) Convert edge indices to int32 + histogram dst degrees.
__global__ void convert_hist_kernel(const void* __restrict__ b0,
                                    const void* __restrict__ b1, int E) {
    int g = blockIdx.y;
    const void* buf = g ? b1 : b0;
    int i = blockIdx.x * blockDim.x + threadIdx.x;
    if (i >= 2 * E) return;
    int v;
    if (g_is64[g]) v = (int)((const long long*)buf)[i];
    else           v = ((const int*)buf)[i];
    g_ei[g][i] = v;
    if (i >= E) atomicAdd(&g_deg[g][v], 1);   // second half = dst
}

// ---------------------------------------------------------------------------
// 1) GEMM: h = x @ W, fused epilogue computes s = h.a_src, t = h.a_dst.
//    BM=128, BN=128 (full), BK=16, 256 threads, 8x8 microtile.
// ---------------------------------------------------------------------------
__global__ __launch_bounds__(256, 2)
void gemm_kernel(const float* __restrict__ x0, const float* __restrict__ W0,
                 const float* __restrict__ as0, const float* __restrict__ ad0,
                 const float* __restrict__ x1, const float* __restrict__ W1,
                 const float* __restrict__ as1, const float* __restrict__ ad1,
                 int N) {
    int g = blockIdx.y;
    const float* __restrict__ x = g ? x1 : x0;
    const float* __restrict__ W = g ? W1 : W0;
    const float* __restrict__ a_src = g ? as1 : as0;
    const float* __restrict__ a_dst = g ? ad1 : ad0;
    float* __restrict__ h = g_h[g];

    __shared__ float xs[16][129];   // [k][row], padded
    __shared__ float ws[16][128];   // [k][col]

    int tid = threadIdx.x;            // 0..255
    int tx = tid & 15;                // col group (8 cols)
    int ty = tid >> 4;                // row group (8 rows)
    int row0 = blockIdx.x * 128;

    float acc[8][8];
#pragma unroll
    for (int i = 0; i < 8; i++)
#pragma unroll
        for (int j = 0; j < 8; j++) acc[i][j] = 0.f;

    for (int k0 = 0; k0 < NODE_D; k0 += 16) {
#pragma unroll
        for (int i = 0; i < 2; i++) {
            int idx = tid + i * 256;          // 0..511
            int r = idx >> 2, kq = idx & 3;   // row, k-quad
            int gr = row0 + r;
            float4 v = (gr < N) ? ((const float4*)x)[gr * (NODE_D / 4) + (k0 >> 2) + kq]
                                : make_float4(0.f, 0.f, 0.f, 0.f);
            xs[kq * 4 + 0][r] = v.x;
            xs[kq * 4 + 1][r] = v.y;
            xs[kq * 4 + 2][r] = v.z;
            xs[kq * 4 + 3][r] = v.w;
        }
#pragma unroll
        for (int i = 0; i < 2; i++) {
            int idx = tid + i * 256;
            int k = idx >> 5, c4 = idx & 31;
            ((float4*)ws[k])[c4] = ((const float4*)W)[(k0 + k) * (NODE_D / 4) + c4];
        }
        __syncthreads();
#pragma unroll
        for (int k = 0; k < 16; k++) {
            float xv[8], wv[8];
#pragma unroll
            for (int i = 0; i < 8; i++) xv[i] = xs[k][ty * 8 + i];
            float4 w0 = ((const float4*)ws[k])[tx * 2];
            float4 w1 = ((const float4*)ws[k])[tx * 2 + 1];
            wv[0] = w0.x; wv[1] = w0.y; wv[2] = w0.z; wv[3] = w0.w;
            wv[4] = w1.x; wv[5] = w1.y; wv[6] = w1.z; wv[7] = w1.w;
#pragma unroll
            for (int i = 0; i < 8; i++)
#pragma unroll
                for (int j = 0; j < 8; j++)
                    acc[i][j] = fmaf(xv[i], wv[j], acc[i][j]);
        }
        __syncthreads();
    }
    // store h
#pragma unroll
    for (int i = 0; i < 8; i++) {
        int gr = row0 + ty * 8 + i;
        if (gr < N) {
            float4 o0 = make_float4(acc[i][0], acc[i][1], acc[i][2], acc[i][3]);
            float4 o1 = make_float4(acc[i][4], acc[i][5], acc[i][6], acc[i][7]);
            ((float4*)h)[gr * (NODE_D / 4) + tx * 2]     = o0;
            ((float4*)h)[gr * (NODE_D / 4) + tx * 2 + 1] = o1;
        }
    }
    // fused dots: partial over this thread's 8 cols, butterfly over 16 lanes
    float as[8], ad[8];
#pragma unroll
    for (int j = 0; j < 8; j++) {
        as[j] = __ldg(a_src + tx * 8 + j);
        ad[j] = __ldg(a_dst + tx * 8 + j);
    }
    float ps[8], pt[8];
#pragma unroll
    for (int i = 0; i < 8; i++) {
        float s = 0.f, t = 0.f;
#pragma unroll
        for (int j = 0; j < 8; j++) {
            s = fmaf(acc[i][j], as[j], s);
            t = fmaf(acc[i][j], ad[j], t);
        }
        ps[i] = s; pt[i] = t;
    }
#pragma unroll
    for (int off = 8; off >= 1; off >>= 1) {
#pragma unroll
        for (int i = 0; i < 8; i++) {
            ps[i] += __shfl_xor_sync(0xffffffffu, ps[i], off);
            pt[i] += __shfl_xor_sync(0xffffffffu, pt[i], off);
        }
    }
    if (tx == 0) {
#pragma unroll
        for (int i = 0; i < 8; i++) {
            int gr = row0 + ty * 8 + i;
            if (gr < N) { g_s[g][gr] = ps[i]; g_t[g][gr] = pt[i]; }
        }
    }
}

// ---------------------------------------------------------------------------
// 2) Exclusive scan of degrees (3 stages)
// ---------------------------------------------------------------------------
__global__ void scanA_kernel(int N) {
    int g = blockIdx.y;
    __shared__ int sh[SCAN_B];
    int t = threadIdx.x;
    int i = blockIdx.x * SCAN_B + t;
    int v = (i < N) ? g_deg[g][i] : 0;
    sh[t] = v;
    __syncthreads();
#pragma unroll
    for (int off = 1; off < SCAN_B; off <<= 1) {
        int u = (t >= off) ? sh[t - off] : 0;
        __syncthreads();
        sh[t] += u;
        __syncthreads();
    }
    if (i < N) g_start[g][i] = sh[t] - v;        // exclusive
    if (t == SCAN_B - 1) g_bsum[g][blockIdx.x] = sh[t];
}

__global__ void scanB_kernel(int nb) {
    int g = blockIdx.y;
    __shared__ int sh[64];
    int t = threadIdx.x;
    int v = (t < nb) ? g_bsum[g][t] : 0;
    sh[t] = v;
    __syncthreads();
#pragma unroll
    for (int off = 1; off < 64; off <<= 1) {
        int u = (t >= off) ? sh[t - off] : 0;
        __syncthreads();
        sh[t] += u;
        __syncthreads();
    }
    if (t < nb) g_bsum[g][t] = sh[t] - v;        // exclusive
}

__global__ void scanC_kernel(int N) {
    int g = blockIdx.y;
    int i = blockIdx.x * SCAN_B + threadIdx.x;
    if (i >= N) return;
    int s = g_start[g][i] + g_bsum[g][blockIdx.x];
    g_start[g][i] = s;
    g_cursor[g][i] = s;
}

// ---------------------------------------------------------------------------
// 3) Scatter src ids into CSR by dst.
// ---------------------------------------------------------------------------
__global__ void scatter_kernel(int E) {
    int g = blockIdx.y;
    int e = blockIdx.x * blockDim.x + threadIdx.x;
    if (e >= E) return;
    int src = g_ei[g][e];
    int dst = g_ei[g][E + e];
    int slot = atomicAdd(&g_cursor[g][dst], 1);
    g_csr[g][slot] = src;
}

// ---------------------------------------------------------------------------
// 4) Fused GAT: one warp per dst node. max -> exp-sum+gather-acc -> finalize.
// ---------------------------------------------------------------------------
__global__ __launch_bounds__(256)
void gat_kernel(float* __restrict__ out_base,
                const float* __restrict__ b0, const float* __restrict__ b1,
                int N) {
    int g = blockIdx.y;
    int warp = (blockIdx.x * blockDim.x + threadIdx.x) >> 5;
    int lane = threadIdx.x & 31;
    if (warp >= N) return;
    const float* bias = g ? b1 : b0;
    float* out = out_base + (size_t)g * N * NODE_D;
    const float* __restrict__ s_arr = g_s[g];
    const int* __restrict__ csr = g_csr[g];

    int start = g_start[g][warp];
    int deg = g_deg[g][warp];
    float tn = g_t[g][warp];
    float eself = leaky(s_arr[warp] + tn);

    // segment max (incl self loop)
    float m = eself;
    for (int i = lane; i < deg; i += 32) {
        int src = csr[start + i];
        m = fmaxf(m, leaky(s_arr[src] + tn));
    }
#pragma unroll
    for (int o = 16; o > 0; o >>= 1)
        m = fmaxf(m, __shfl_xor_sync(0xffffffffu, m, o));

    // accumulate: self first
    float den = __expf(eself - m);
    float4 hn = ((const float4*)(g_h[g] + (size_t)warp * NODE_D))[lane];
    float4 acc = make_float4(den * hn.x, den * hn.y, den * hn.z, den * hn.w);

    for (int i = 0; i < deg; i++) {
        int src = csr[start + i];
        float ex = __expf(leaky(s_arr[src] + tn) - m);
        float4 hv = ((const float4*)(g_h[g] + (size_t)src * NODE_D))[lane];
        acc.x = fmaf(ex, hv.x, acc.x);
        acc.y = fmaf(ex, hv.y, acc.y);
        acc.z = fmaf(ex, hv.z, acc.z);
        acc.w = fmaf(ex, hv.w, acc.w);
        den += ex;
    }

    float inv = 1.f / (den + 1e-16f);
    float4 bv = ((const float4*)bias)[lane];
    float4 o;
    o.x = fmaxf(fmaf(acc.x, inv, bv.x), 0.f);
    o.y = fmaxf(fmaf(acc.y, inv, bv.y), 0.f);
    o.z = fmaxf(fmaf(acc.z, inv, bv.z), 0.f);
    o.w = fmaxf(fmaf(acc.w, inv, bv.w), 0.f);
    ((float4*)(out + (size_t)warp * NODE_D))[lane] = o;
}

// ---------------------------------------------------------------------------
extern "C" void kernel_launch(void* const* d_in, const int* in_sizes, int n_in,
                              void* d_out, int out_size) {
    const float* x1  = (const float*)d_in[0];
    const void*  ei1 = d_in[1];
    const float* x2  = (const float*)d_in[3];
    const void*  ei2 = d_in[4];
    const float* W1  = (const float*)d_in[6];
    const float* as1 = (const float*)d_in[7];
    const float* ad1 = (const float*)d_in[8];
    const float* b1  = (const float*)d_in[9];
    const float* W2  = (const float*)d_in[10];
    const float* as2 = (const float*)d_in[11];
    const float* ad2 = (const float*)d_in[12];
    const float* b2  = (const float*)d_in[13];

    int N = in_sizes[0] / NODE_D;
    int E = in_sizes[1] / 2;
    int nb = (N + SCAN_B - 1) / SCAN_B;

    float* out = (float*)d_out;

    dim3 zero_grid((N + 1023) / 1024, 2);
    dim3 conv_grid((2 * E + 255) / 256, 2);
    dim3 gemm_grid((N + 127) / 128, 2);
    dim3 scan_grid(nb, 2);
    dim3 one_grid(1, 2);
    dim3 scat_grid((E + 255) / 256, 2);
    dim3 gat_grid((N + 7) / 8, 2);          // 8 warps / block

    probe_kernel<<<1, 2>>>((const unsigned int*)ei1, (const unsigned int*)ei2);
    zero_deg_kernel<<<zero_grid, 1024>>>(N);
    convert_hist_kernel<<<conv_grid, 256>>>(ei1, ei2, E);
    gemm_kernel<<<gemm_grid, 256>>>(x1, W1, as1, ad1, x2, W2, as2, ad2, N);
    scanA_kernel<<<scan_grid, SCAN_B>>>(N);
    scanB_kernel<<<one_grid, 64>>>(nb);
    scanC_kernel<<<scan_grid, SCAN_B>>>(N);
    scatter_kernel<<<scat_grid, 256>>>(E);
    gat_kernel<<<gat_grid, 256>>>(out, b1, b2, N);
}

// round 5
// speedup vs baseline: 2.3838x; 1.1306x over previous
#include <cuda_runtime.h>
#include <cuda_fp16.h>
#include <cuda_bf16.h>

#define NODE_D 128
#define NMAX   50048
#define EMAX   600064
#define SCAN_B 1024
#define GBK    32
#define XPAD   8

// Scratch (device globals: no allocations allowed)
__device__ float g_h[2][NMAX * NODE_D];   // projected features
__device__ float g_s[2][NMAX];            // h . a_src
__device__ float g_t[2][NMAX];            // h . a_dst
__device__ int   g_deg[2][NMAX];          // in-degree (excl self loop)
__device__ int   g_start[2][NMAX];        // CSR row start
__device__ int   g_cursor[2][NMAX];       // scatter cursor
__device__ int   g_csr[2][EMAX];          // src ids grouped by dst
__device__ int   g_ei[2][2 * EMAX];       // int32 edge indices (converted)
__device__ int   g_is64[2];               // dtype probe result
__device__ int   g_bsum[2][64];           // scan block sums

__device__ __forceinline__ float leaky(float x) { return x > 0.f ? x : 0.2f * x; }

__device__ __forceinline__ void ldsm4(unsigned r[4], const void* p) {
    unsigned a = (unsigned)__cvta_generic_to_shared(p);
    asm volatile("ldmatrix.sync.aligned.m8n8.x4.shared.b16 {%0,%1,%2,%3},[%4];"
                 : "=r"(r[0]), "=r"(r[1]), "=r"(r[2]), "=r"(r[3]) : "r"(a));
}
__device__ __forceinline__ void ldsm4t(unsigned r[4], const void* p) {
    unsigned a = (unsigned)__cvta_generic_to_shared(p);
    asm volatile("ldmatrix.sync.aligned.m8n8.x4.trans.shared.b16 {%0,%1,%2,%3},[%4];"
                 : "=r"(r[0]), "=r"(r[1]), "=r"(r[2]), "=r"(r[3]) : "r"(a));
}
__device__ __forceinline__ void mma16816(float c[4], const unsigned a[4], const unsigned b[2]) {
    asm volatile("mma.sync.aligned.m16n8k16.row.col.f32.f16.f16.f32 "
                 "{%0,%1,%2,%3},{%4,%5,%6,%7},{%8,%9},{%0,%1,%2,%3};"
                 : "+f"(c[0]), "+f"(c[1]), "+f"(c[2]), "+f"(c[3])
                 : "r"(a[0]), "r"(a[1]), "r"(a[2]), "r"(a[3]), "r"(b[0]), "r"(b[1]));
}

// ---------------------------------------------------------------------------
// 0a) Probe both edge buffers: int64 (all hi-words zero) vs int32.
// ---------------------------------------------------------------------------
__global__ void probe_kernel(const unsigned int* __restrict__ b0,
                             const unsigned int* __restrict__ b1) {
    int g = threadIdx.x;
    if (g >= 2) return;
    const unsigned int* buf = g ? b1 : b0;
    int nz = 0;
#pragma unroll
    for (int i = 0; i < 32; i++) nz += (buf[2 * i + 1] != 0u);
    g_is64[g] = (nz == 0) ? 1 : 0;
}

// 0b) Zero degree counters + s/t accumulators (graph replays need this).
__global__ void zero_kernel(int N) {
    int g = blockIdx.y;
    int i = blockIdx.x * blockDim.x + threadIdx.x;
    if (i < N) { g_deg[g][i] = 0; g_s[g][i] = 0.f; g_t[g][i] = 0.f; }
}

// 0c) Convert edge indices to int32 + histogram dst degrees.
__global__ void convert_hist_kernel(const void* __restrict__ b0,
                                    const void* __restrict__ b1, int E) {
    int g = blockIdx.y;
    const void* buf = g ? b1 : b0;
    int i = blockIdx.x * blockDim.x + threadIdx.x;
    if (i >= 2 * E) return;
    int v;
    if (g_is64[g]) v = (int)((const long long*)buf)[i];
    else           v = ((const int*)buf)[i];
    g_ei[g][i] = v;
    if (i >= E) atomicAdd(&g_deg[g][v], 1);   // second half = dst
}

// ---------------------------------------------------------------------------
// 1) GEMM via fp16 split tensor-core MMA: h = x @ W (+ fused s,t dots).
//    x = x_hi + x_lo (fp16), W likewise; acc = xh*Wh + xh*Wl + xl*Wh (fp32).
//    BM=128, BN=128, BK=32; 8 warps, warp tile 32x64 (m16n8k16 frags).
// ---------------------------------------------------------------------------
__global__ __launch_bounds__(256)
void gemm_kernel(const float* __restrict__ x0, const float* __restrict__ W0,
                 const float* __restrict__ as0, const float* __restrict__ ad0,
                 const float* __restrict__ x1, const float* __restrict__ W1,
                 const float* __restrict__ as1, const float* __restrict__ ad1,
                 int N) {
    int g = blockIdx.y;
    const float* __restrict__ x = g ? x1 : x0;
    const float* __restrict__ W = g ? W1 : W0;
    const float* __restrict__ a_src = g ? as1 : as0;
    const float* __restrict__ a_dst = g ? ad1 : ad0;
    float* __restrict__ h = g_h[g];

    __shared__ __half xs_hi[128][GBK + XPAD];
    __shared__ __half xs_lo[128][GBK + XPAD];
    __shared__ __half ws_hi[GBK][128 + XPAD];
    __shared__ __half ws_lo[GBK][128 + XPAD];

    int tid = threadIdx.x;
    int lane = tid & 31;
    int wid = tid >> 5;
    int warpM = wid >> 1;              // 0..3
    int warpN = wid & 1;               // 0..1
    int row0 = blockIdx.x * 128;

    float acc[2][8][4];
#pragma unroll
    for (int mi = 0; mi < 2; mi++)
#pragma unroll
        for (int ni = 0; ni < 8; ni++)
#pragma unroll
            for (int q = 0; q < 4; q++) acc[mi][ni][q] = 0.f;

    for (int k0 = 0; k0 < NODE_D; k0 += GBK) {
        // stage x tile (128 x 32): 1024 float4, 4 per thread, split hi/lo
#pragma unroll
        for (int i = 0; i < 4; i++) {
            int idx = tid + i * 256;
            int r = idx >> 3, kq = idx & 7;
            int gr = row0 + r;
            float4 v = (gr < N) ? ((const float4*)x)[gr * (NODE_D / 4) + (k0 >> 2) + kq]
                                : make_float4(0.f, 0.f, 0.f, 0.f);
            float vv[4] = {v.x, v.y, v.z, v.w};
#pragma unroll
            for (int j = 0; j < 4; j++) {
                __half hi = __float2half_rn(vv[j]);
                xs_hi[r][kq * 4 + j] = hi;
                xs_lo[r][kq * 4 + j] = __float2half_rn(vv[j] - __half2float(hi));
            }
        }
        // stage W tile (32 x 128)
#pragma unroll
        for (int i = 0; i < 4; i++) {
            int idx = tid + i * 256;
            int k = idx >> 5, c4 = idx & 31;
            float4 v = ((const float4*)W)[(k0 + k) * (NODE_D / 4) + c4];
            float vv[4] = {v.x, v.y, v.z, v.w};
#pragma unroll
            for (int j = 0; j < 4; j++) {
                __half hi = __float2half_rn(vv[j]);
                ws_hi[k][c4 * 4 + j] = hi;
                ws_lo[k][c4 * 4 + j] = __float2half_rn(vv[j] - __half2float(hi));
            }
        }
        __syncthreads();

#pragma unroll
        for (int ks = 0; ks < GBK / 16; ks++) {
            int kb = ks * 16;
            unsigned a_hi[2][4], a_lo[2][4];
#pragma unroll
            for (int mi = 0; mi < 2; mi++) {
                int ar = warpM * 32 + mi * 16 + (lane & 15);
                int ac = kb + (lane >> 4) * 8;
                ldsm4(a_hi[mi], &xs_hi[ar][ac]);
                ldsm4(a_lo[mi], &xs_lo[ar][ac]);
            }
            unsigned b_hi[8][2], b_lo[8][2];
#pragma unroll
            for (int np = 0; np < 4; np++) {
                int br = kb + (lane & 15);
                int bc = warpN * 64 + np * 16 + (lane >> 4) * 8;
                unsigned r4[4];
                ldsm4t(r4, &ws_hi[br][bc]);
                b_hi[np * 2][0] = r4[0]; b_hi[np * 2][1] = r4[1];
                b_hi[np * 2 + 1][0] = r4[2]; b_hi[np * 2 + 1][1] = r4[3];
                ldsm4t(r4, &ws_lo[br][bc]);
                b_lo[np * 2][0] = r4[0]; b_lo[np * 2][1] = r4[1];
                b_lo[np * 2 + 1][0] = r4[2]; b_lo[np * 2 + 1][1] = r4[3];
            }
#pragma unroll
            for (int mi = 0; mi < 2; mi++)
#pragma unroll
                for (int ni = 0; ni < 8; ni++) {
                    mma16816(acc[mi][ni], a_hi[mi], b_hi[ni]);
                    mma16816(acc[mi][ni], a_hi[mi], b_lo[ni]);
                    mma16816(acc[mi][ni], a_lo[mi], b_hi[ni]);
                }
        }
        __syncthreads();
    }

    // epilogue: store h + fused s,t dot partials
    int groupId = lane >> 2, tid4 = lane & 3;
    float ps[4] = {0.f, 0.f, 0.f, 0.f};
    float pt[4] = {0.f, 0.f, 0.f, 0.f};
#pragma unroll
    for (int ni = 0; ni < 8; ni++) {
        int col = warpN * 64 + ni * 8 + tid4 * 2;
        float sa0 = __ldg(a_src + col), sa1 = __ldg(a_src + col + 1);
        float da0 = __ldg(a_dst + col), da1 = __ldg(a_dst + col + 1);
#pragma unroll
        for (int mi = 0; mi < 2; mi++) {
            int row = row0 + warpM * 32 + mi * 16 + groupId;
            float c0 = acc[mi][ni][0], c1 = acc[mi][ni][1];
            float c2 = acc[mi][ni][2], c3 = acc[mi][ni][3];
            if (row < N)     *(float2*)(h + (size_t)row * NODE_D + col) = make_float2(c0, c1);
            if (row + 8 < N) *(float2*)(h + (size_t)(row + 8) * NODE_D + col) = make_float2(c2, c3);
            ps[mi * 2 + 0] += c0 * sa0 + c1 * sa1;
            ps[mi * 2 + 1] += c2 * sa0 + c3 * sa1;
            pt[mi * 2 + 0] += c0 * da0 + c1 * da1;
            pt[mi * 2 + 1] += c2 * da0 + c3 * da1;
        }
    }
#pragma unroll
    for (int off = 1; off <= 2; off <<= 1) {
#pragma unroll
        for (int q = 0; q < 4; q++) {
            ps[q] += __shfl_xor_sync(0xffffffffu, ps[q], off);
            pt[q] += __shfl_xor_sync(0xffffffffu, pt[q], off);
        }
    }
    if (tid4 == 0) {
#pragma unroll
        for (int mi = 0; mi < 2; mi++)
#pragma unroll
            for (int hf = 0; hf < 2; hf++) {
                int row = row0 + warpM * 32 + mi * 16 + hf * 8 + groupId;
                if (row < N) {
                    atomicAdd(&g_s[g][row], ps[mi * 2 + hf]);
                    atomicAdd(&g_t[g][row], pt[mi * 2 + hf]);
                }
            }
    }
}

// ---------------------------------------------------------------------------
// 2) Exclusive scan of degrees (3 stages)
// ---------------------------------------------------------------------------
__global__ void scanA_kernel(int N) {
    int g = blockIdx.y;
    __shared__ int sh[SCAN_B];
    int t = threadIdx.x;
    int i = blockIdx.x * SCAN_B + t;
    int v = (i < N) ? g_deg[g][i] : 0;
    sh[t] = v;
    __syncthreads();
#pragma unroll
    for (int off = 1; off < SCAN_B; off <<= 1) {
        int u = (t >= off) ? sh[t - off] : 0;
        __syncthreads();
        sh[t] += u;
        __syncthreads();
    }
    if (i < N) g_start[g][i] = sh[t] - v;        // exclusive
    if (t == SCAN_B - 1) g_bsum[g][blockIdx.x] = sh[t];
}

__global__ void scanB_kernel(int nb) {
    int g = blockIdx.y;
    __shared__ int sh[64];
    int t = threadIdx.x;
    int v = (t < nb) ? g_bsum[g][t] : 0;
    sh[t] = v;
    __syncthreads();
#pragma unroll
    for (int off = 1; off < 64; off <<= 1) {
        int u = (t >= off) ? sh[t - off] : 0;
        __syncthreads();
        sh[t] += u;
        __syncthreads();
    }
    if (t < nb) g_bsum[g][t] = sh[t] - v;        // exclusive
}

__global__ void scanC_kernel(int N) {
    int g = blockIdx.y;
    int i = blockIdx.x * SCAN_B + threadIdx.x;
    if (i >= N) return;
    int s = g_start[g][i] + g_bsum[g][blockIdx.x];
    g_start[g][i] = s;
    g_cursor[g][i] = s;
}

// ---------------------------------------------------------------------------
// 3) Scatter src ids into CSR by dst.
// ---------------------------------------------------------------------------
__global__ void scatter_kernel(int E) {
    int g = blockIdx.y;
    int e = blockIdx.x * blockDim.x + threadIdx.x;
    if (e >= E) return;
    int src = g_ei[g][e];
    int dst = g_ei[g][E + e];
    int slot = atomicAdd(&g_cursor[g][dst], 1);
    g_csr[g][slot] = src;
}

// ---------------------------------------------------------------------------
// 4) Fused GAT: one warp per dst node. max -> exp-sum+gather-acc -> finalize.
// ---------------------------------------------------------------------------
__global__ __launch_bounds__(256)
void gat_kernel(float* __restrict__ out_base,
                const float* __restrict__ b0, const float* __restrict__ b1,
                int N) {
    int g = blockIdx.y;
    int warp = (blockIdx.x * blockDim.x + threadIdx.x) >> 5;
    int lane = threadIdx.x & 31;
    if (warp >= N) return;
    const float* bias = g ? b1 : b0;
    float* out = out_base + (size_t)g * N * NODE_D;
    const float* __restrict__ s_arr = g_s[g];
    const int* __restrict__ csr = g_csr[g];

    int start = g_start[g][warp];
    int deg = g_deg[g][warp];
    float tn = g_t[g][warp];
    float eself = leaky(s_arr[warp] + tn);

    // segment max (incl self loop)
    float m = eself;
    for (int i = lane; i < deg; i += 32) {
        int src = csr[start + i];
        m = fmaxf(m, leaky(s_arr[src] + tn));
    }
#pragma unroll
    for (int o = 16; o > 0; o >>= 1)
        m = fmaxf(m, __shfl_xor_sync(0xffffffffu, m, o));

    // accumulate: self first
    float den = __expf(eself - m);
    float4 hn = ((const float4*)(g_h[g] + (size_t)warp * NODE_D))[lane];
    float4 acc = make_float4(den * hn.x, den * hn.y, den * hn.z, den * hn.w);

    for (int i = 0; i < deg; i++) {
        int src = csr[start + i];
        float ex = __expf(leaky(s_arr[src] + tn) - m);
        float4 hv = ((const float4*)(g_h[g] + (size_t)src * NODE_D))[lane];
        acc.x = fmaf(ex, hv.x, acc.x);
        acc.y = fmaf(ex, hv.y, acc.y);
        acc.z = fmaf(ex, hv.z, acc.z);
        acc.w = fmaf(ex, hv.w, acc.w);
        den += ex;
    }

    float inv = 1.f / (den + 1e-16f);
    float4 bv = ((const float4*)bias)[lane];
    float4 o;
    o.x = fmaxf(fmaf(acc.x, inv, bv.x), 0.f);
    o.y = fmaxf(fmaf(acc.y, inv, bv.y), 0.f);
    o.z = fmaxf(fmaf(acc.z, inv, bv.z), 0.f);
    o.w = fmaxf(fmaf(acc.w, inv, bv.w), 0.f);
    ((float4*)(out + (size_t)warp * NODE_D))[lane] = o;
}

// ---------------------------------------------------------------------------
extern "C" void kernel_launch(void* const* d_in, const int* in_sizes, int n_in,
                              void* d_out, int out_size) {
    const float* x1  = (const float*)d_in[0];
    const void*  ei1 = d_in[1];
    const float* x2  = (const float*)d_in[3];
    const void*  ei2 = d_in[4];
    const float* W1  = (const float*)d_in[6];
    const float* as1 = (const float*)d_in[7];
    const float* ad1 = (const float*)d_in[8];
    const float* b1  = (const float*)d_in[9];
    const float* W2  = (const float*)d_in[10];
    const float* as2 = (const float*)d_in[11];
    const float* ad2 = (const float*)d_in[12];
    const float* b2  = (const float*)d_in[13];

    int N = in_sizes[0] / NODE_D;
    int E = in_sizes[1] / 2;
    int nb = (N + SCAN_B - 1) / SCAN_B;

    float* out = (float*)d_out;

    dim3 zero_grid((N + 1023) / 1024, 2);
    dim3 conv_grid((2 * E + 255) / 256, 2);
    dim3 gemm_grid((N + 127) / 128, 2);
    dim3 scan_grid(nb, 2);
    dim3 one_grid(1, 2);
    dim3 scat_grid((E + 255) / 256, 2);
    dim3 gat_grid((N + 7) / 8, 2);          // 8 warps / block

    probe_kernel<<<1, 2>>>((const unsigned int*)ei1, (const unsigned int*)ei2);
    zero_kernel<<<zero_grid, 1024>>>(N);
    convert_hist_kernel<<<conv_grid, 256>>>(ei1, ei2, E);
    gemm_kernel<<<gemm_grid, 256>>>(x1, W1, as1, ad1, x2, W2, as2, ad2, N);
    scanA_kernel<<<scan_grid, SCAN_B>>>(N);
    scanB_kernel<<<one_grid, 64>>>(nb);
    scanC_kernel<<<scan_grid, SCAN_B>>>(N);
    scatter_kernel<<<scat_grid, 256>>>(E);
    gat_kernel<<<gat_grid, 256>>>(out, b1, b2, N);
}

// round 8
// speedup vs baseline: 2.7761x; 1.1646x over previous
#include <cuda_runtime.h>
#include <cuda_fp16.h>
#include <cuda_bf16.h>

#define NODE_D 128
#define NMAX   50048
#define EMAX   600064
#define SCAN_B 1024
#define GBK    64
#define XPAD   8

// dynamic smem layout (in __half units)
#define XS_W   (GBK + XPAD)       // 72
#define WS_W   (128 + XPAD)       // 136
#define OFF_XHI 0
#define OFF_XLO (128 * XS_W)
#define OFF_WHI (2 * 128 * XS_W)
#define OFF_WLO (2 * 128 * XS_W + GBK * WS_W)
#define SMEM_HALVES (2 * 128 * XS_W + 2 * GBK * WS_W)
#define SMEM_BYTES  (SMEM_HALVES * 2)

// Scratch (device globals: no allocations allowed)
__device__ float g_h[2][NMAX * NODE_D];   // projected features
__device__ float g_s[2][NMAX];            // h . a_src
__device__ float g_t[2][NMAX];            // h . a_dst
__device__ int   g_deg[2][NMAX];          // in-degree (excl self loop)
__device__ int   g_start[2][NMAX];        // CSR row start
__device__ int   g_cursor[2][NMAX];       // scatter cursor
__device__ int   g_csr[2][EMAX];          // src ids grouped by dst
__device__ int   g_ei[2][2 * EMAX];       // int32 edge indices (converted)
__device__ int   g_is64[2];               // dtype probe result
__device__ int   g_bsum[2][64];           // scan block sums

__device__ __forceinline__ float leaky(float x) { return x > 0.f ? x : 0.2f * x; }

__device__ __forceinline__ void ldsm4(unsigned r[4], const void* p) {
    unsigned a = (unsigned)__cvta_generic_to_shared(p);
    asm volatile("ldmatrix.sync.aligned.m8n8.x4.shared.b16 {%0,%1,%2,%3},[%4];"
                 : "=r"(r[0]), "=r"(r[1]), "=r"(r[2]), "=r"(r[3]) : "r"(a));
}
__device__ __forceinline__ void ldsm4t(unsigned r[4], const void* p) {
    unsigned a = (unsigned)__cvta_generic_to_shared(p);
    asm volatile("ldmatrix.sync.aligned.m8n8.x4.trans.shared.b16 {%0,%1,%2,%3},[%4];"
                 : "=r"(r[0]), "=r"(r[1]), "=r"(r[2]), "=r"(r[3]) : "r"(a));
}
__device__ __forceinline__ void mma16816(float c[4], const unsigned a[4], const unsigned b0, const unsigned b1) {
    asm volatile("mma.sync.aligned.m16n8k16.row.col.f32.f16.f16.f32 "
                 "{%0,%1,%2,%3},{%4,%5,%6,%7},{%8,%9},{%0,%1,%2,%3};"
                 : "+f"(c[0]), "+f"(c[1]), "+f"(c[2]), "+f"(c[3])
                 : "r"(a[0]), "r"(a[1]), "r"(a[2]), "r"(a[3]), "r"(b0), "r"(b1));
}

// ---------------------------------------------------------------------------
// 0a) Probe both edge buffers: int64 (all hi-words zero) vs int32.
// ---------------------------------------------------------------------------
__global__ void probe_kernel(const unsigned int* __restrict__ b0,
                             const unsigned int* __restrict__ b1) {
    int g = threadIdx.x;
    if (g >= 2) return;
    const unsigned int* buf = g ? b1 : b0;
    int nz = 0;
#pragma unroll
    for (int i = 0; i < 32; i++) nz += (buf[2 * i + 1] != 0u);
    g_is64[g] = (nz == 0) ? 1 : 0;
}

// 0b) Zero degree counters + s/t accumulators (graph replays need this).
__global__ void zero_kernel(int N) {
    int g = blockIdx.y;
    int i = blockIdx.x * blockDim.x + threadIdx.x;
    if (i < N) { g_deg[g][i] = 0; g_s[g][i] = 0.f; g_t[g][i] = 0.f; }
}

// 0c) Convert edge indices to int32 + histogram dst degrees.
__global__ void convert_hist_kernel(const void* __restrict__ b0,
                                    const void* __restrict__ b1, int E) {
    int g = blockIdx.y;
    const void* buf = g ? b1 : b0;
    int i = blockIdx.x * blockDim.x + threadIdx.x;
    if (i >= 2 * E) return;
    int v;
    if (g_is64[g]) v = (int)((const long long*)buf)[i];
    else           v = ((const int*)buf)[i];
    g_ei[g][i] = v;
    if (i >= E) atomicAdd(&g_deg[g][v], 1);   // second half = dst
}

// ---------------------------------------------------------------------------
// 1) GEMM via fp16 split tensor-core MMA: h = x @ W (+ fused s,t dots).
//    acc = xh*Wh + xh*Wl + xl*Wh (fp32). BM=128, BN=128, BK=64; 8 warps,
//    warp tile 32x64. Dynamic smem; 2 blocks/SM (regs<=128).
// ---------------------------------------------------------------------------
__global__ __launch_bounds__(256, 2)
void gemm_kernel(const float* __restrict__ x0, const float* __restrict__ W0,
                 const float* __restrict__ as0, const float* __restrict__ ad0,
                 const float* __restrict__ x1, const float* __restrict__ W1,
                 const float* __restrict__ as1, const float* __restrict__ ad1,
                 int N) {
    extern __shared__ __half smem[];
    __half* xs_hi = smem + OFF_XHI;   // [128][XS_W]
    __half* xs_lo = smem + OFF_XLO;
    __half* ws_hi = smem + OFF_WHI;   // [GBK][WS_W]
    __half* ws_lo = smem + OFF_WLO;

    int g = blockIdx.y;
    const float* __restrict__ x = g ? x1 : x0;
    const float* __restrict__ W = g ? W1 : W0;
    const float* __restrict__ a_src = g ? as1 : as0;
    const float* __restrict__ a_dst = g ? ad1 : ad0;
    float* __restrict__ h = g_h[g];

    int tid = threadIdx.x;
    int lane = tid & 31;
    int wid = tid >> 5;
    int warpM = wid >> 1;              // 0..3
    int warpN = wid & 1;               // 0..1
    int row0 = blockIdx.x * 128;

    float acc[2][8][4];
#pragma unroll
    for (int mi = 0; mi < 2; mi++)
#pragma unroll
        for (int ni = 0; ni < 8; ni++)
#pragma unroll
            for (int q = 0; q < 4; q++) acc[mi][ni][q] = 0.f;

    for (int k0 = 0; k0 < NODE_D; k0 += GBK) {
        // stage x tile (128 x 64): 2048 float4, 8 per thread, split hi/lo
#pragma unroll
        for (int i = 0; i < 8; i++) {
            int idx = tid + i * 256;
            int r = idx >> 4, kq = idx & 15;
            int gr = row0 + r;
            float4 v = (gr < N) ? ((const float4*)x)[gr * (NODE_D / 4) + (k0 >> 2) + kq]
                                : make_float4(0.f, 0.f, 0.f, 0.f);
            float vv[4] = {v.x, v.y, v.z, v.w};
#pragma unroll
            for (int j = 0; j < 4; j++) {
                __half hi = __float2half_rn(vv[j]);
                xs_hi[r * XS_W + kq * 4 + j] = hi;
                xs_lo[r * XS_W + kq * 4 + j] = __float2half_rn(vv[j] - __half2float(hi));
            }
        }
        // stage W tile (64 x 128): 2048 float4, 8 per thread
#pragma unroll
        for (int i = 0; i < 8; i++) {
            int idx = tid + i * 256;
            int k = idx >> 5, c4 = idx & 31;
            float4 v = ((const float4*)W)[(k0 + k) * (NODE_D / 4) + c4];
            float vv[4] = {v.x, v.y, v.z, v.w};
#pragma unroll
            for (int j = 0; j < 4; j++) {
                __half hi = __float2half_rn(vv[j]);
                ws_hi[k * WS_W + c4 * 4 + j] = hi;
                ws_lo[k * WS_W + c4 * 4 + j] = __float2half_rn(vv[j] - __half2float(hi));
            }
        }
        __syncthreads();

#pragma unroll
        for (int ks = 0; ks < GBK / 16; ks++) {
            int kb = ks * 16;
            unsigned a_hi[2][4], a_lo[2][4];
#pragma unroll
            for (int mi = 0; mi < 2; mi++) {
                int ar = warpM * 32 + mi * 16 + (lane & 15);
                int ac = kb + (lane >> 4) * 8;
                ldsm4(a_hi[mi], &xs_hi[ar * XS_W + ac]);
                ldsm4(a_lo[mi], &xs_lo[ar * XS_W + ac]);
            }
            // only one B hi/lo fragment pair live at a time (keeps regs <= 128)
#pragma unroll
            for (int np = 0; np < 4; np++) {
                int br = kb + (lane & 15);
                int bc = warpN * 64 + np * 16 + (lane >> 4) * 8;
                unsigned bh[4], bl[4];
                ldsm4t(bh, &ws_hi[br * WS_W + bc]);
                ldsm4t(bl, &ws_lo[br * WS_W + bc]);
#pragma unroll
                for (int mi = 0; mi < 2; mi++) {
                    mma16816(acc[mi][np * 2 + 0], a_hi[mi], bh[0], bh[1]);
                    mma16816(acc[mi][np * 2 + 1], a_hi[mi], bh[2], bh[3]);
                    mma16816(acc[mi][np * 2 + 0], a_hi[mi], bl[0], bl[1]);
                    mma16816(acc[mi][np * 2 + 1], a_hi[mi], bl[2], bl[3]);
                    mma16816(acc[mi][np * 2 + 0], a_lo[mi], bh[0], bh[1]);
                    mma16816(acc[mi][np * 2 + 1], a_lo[mi], bh[2], bh[3]);
                }
            }
        }
        __syncthreads();
    }

    // epilogue: store h + fused s,t dot partials
    int groupId = lane >> 2, tid4 = lane & 3;
    float ps[4] = {0.f, 0.f, 0.f, 0.f};
    float pt[4] = {0.f, 0.f, 0.f, 0.f};
#pragma unroll
    for (int ni = 0; ni < 8; ni++) {
        int col = warpN * 64 + ni * 8 + tid4 * 2;
        float sa0 = __ldg(a_src + col), sa1 = __ldg(a_src + col + 1);
        float da0 = __ldg(a_dst + col), da1 = __ldg(a_dst + col + 1);
#pragma unroll
        for (int mi = 0; mi < 2; mi++) {
            int row = row0 + warpM * 32 + mi * 16 + groupId;
            float c0 = acc[mi][ni][0], c1 = acc[mi][ni][1];
            float c2 = acc[mi][ni][2], c3 = acc[mi][ni][3];
            if (row < N)     *(float2*)(h + (size_t)row * NODE_D + col) = make_float2(c0, c1);
            if (row + 8 < N) *(float2*)(h + (size_t)(row + 8) * NODE_D + col) = make_float2(c2, c3);
            ps[mi * 2 + 0] += c0 * sa0 + c1 * sa1;
            ps[mi * 2 + 1] += c2 * sa0 + c3 * sa1;
            pt[mi * 2 + 0] += c0 * da0 + c1 * da1;
            pt[mi * 2 + 1] += c2 * da0 + c3 * da1;
        }
    }
#pragma unroll
    for (int off = 1; off <= 2; off <<= 1) {
#pragma unroll
        for (int q = 0; q < 4; q++) {
            ps[q] += __shfl_xor_sync(0xffffffffu, ps[q], off);
            pt[q] += __shfl_xor_sync(0xffffffffu, pt[q], off);
        }
    }
    if (tid4 == 0) {
#pragma unroll
        for (int mi = 0; mi < 2; mi++)
#pragma unroll
            for (int hf = 0; hf < 2; hf++) {
                int row = row0 + warpM * 32 + mi * 16 + hf * 8 + groupId;
                if (row < N) {
                    atomicAdd(&g_s[g][row], ps[mi * 2 + hf]);
                    atomicAdd(&g_t[g][row], pt[mi * 2 + hf]);
                }
            }
    }
}

// ---------------------------------------------------------------------------
// 2) Exclusive scan of degrees (3 stages)
// ---------------------------------------------------------------------------
__global__ void scanA_kernel(int N) {
    int g = blockIdx.y;
    __shared__ int sh[SCAN_B];
    int t = threadIdx.x;
    int i = blockIdx.x * SCAN_B + t;
    int v = (i < N) ? g_deg[g][i] : 0;
    sh[t] = v;
    __syncthreads();
#pragma unroll
    for (int off = 1; off < SCAN_B; off <<= 1) {
        int u = (t >= off) ? sh[t - off] : 0;
        __syncthreads();
        sh[t] += u;
        __syncthreads();
    }
    if (i < N) g_start[g][i] = sh[t] - v;        // exclusive
    if (t == SCAN_B - 1) g_bsum[g][blockIdx.x] = sh[t];
}

__global__ void scanB_kernel(int nb) {
    int g = blockIdx.y;
    __shared__ int sh[64];
    int t = threadIdx.x;
    int v = (t < nb) ? g_bsum[g][t] : 0;
    sh[t] = v;
    __syncthreads();
#pragma unroll
    for (int off = 1; off < 64; off <<= 1) {
        int u = (t >= off) ? sh[t - off] : 0;
        __syncthreads();
        sh[t] += u;
        __syncthreads();
    }
    if (t < nb) g_bsum[g][t] = sh[t] - v;        // exclusive
}

__global__ void scanC_kernel(int N) {
    int g = blockIdx.y;
    int i = blockIdx.x * SCAN_B + threadIdx.x;
    if (i >= N) return;
    int s = g_start[g][i] + g_bsum[g][blockIdx.x];
    g_start[g][i] = s;
    g_cursor[g][i] = s;
}

// ---------------------------------------------------------------------------
// 3) Scatter src ids into CSR by dst.
// ---------------------------------------------------------------------------
__global__ void scatter_kernel(int E) {
    int g = blockIdx.y;
    int e = blockIdx.x * blockDim.x + threadIdx.x;
    if (e >= E) return;
    int src = g_ei[g][e];
    int dst = g_ei[g][E + e];
    int slot = atomicAdd(&g_cursor[g][dst], 1);
    g_csr[g][slot] = src;
}

// ---------------------------------------------------------------------------
// 4) Fused GAT: one warp per dst node. max -> exp-sum+gather-acc -> finalize.
// ---------------------------------------------------------------------------
__global__ __launch_bounds__(256)
void gat_kernel(float* __restrict__ out_base,
                const float* __restrict__ b0, const float* __restrict__ b1,
                int N) {
    int g = blockIdx.y;
    int warp = (blockIdx.x * blockDim.x + threadIdx.x) >> 5;
    int lane = threadIdx.x & 31;
    if (warp >= N) return;
    const float* bias = g ? b1 : b0;
    float* out = out_base + (size_t)g * N * NODE_D;
    const float* __restrict__ s_arr = g_s[g];
    const int* __restrict__ csr = g_csr[g];

    int start = g_start[g][warp];
    int deg = g_deg[g][warp];
    float tn = g_t[g][warp];
    float eself = leaky(s_arr[warp] + tn);

    // segment max (incl self loop)
    float m = eself;
    for (int i = lane; i < deg; i += 32) {
        int src = csr[start + i];
        m = fmaxf(m, leaky(s_arr[src] + tn));
    }
#pragma unroll
    for (int o = 16; o > 0; o >>= 1)
        m = fmaxf(m, __shfl_xor_sync(0xffffffffu, m, o));

    // accumulate: self first
    float den = __expf(eself - m);
    float4 hn = ((const float4*)(g_h[g] + (size_t)warp * NODE_D))[lane];
    float4 acc = make_float4(den * hn.x, den * hn.y, den * hn.z, den * hn.w);

    for (int i = 0; i < deg; i++) {
        int src = csr[start + i];
        float ex = __expf(leaky(s_arr[src] + tn) - m);
        float4 hv = ((const float4*)(g_h[g] + (size_t)src * NODE_D))[lane];
        acc.x = fmaf(ex, hv.x, acc.x);
        acc.y = fmaf(ex, hv.y, acc.y);
        acc.z = fmaf(ex, hv.z, acc.z);
        acc.w = fmaf(ex, hv.w, acc.w);
        den += ex;
    }

    float inv = 1.f / (den + 1e-16f);
    float4 bv = ((const float4*)bias)[lane];
    float4 o;
    o.x = fmaxf(fmaf(acc.x, inv, bv.x), 0.f);
    o.y = fmaxf(fmaf(acc.y, inv, bv.y), 0.f);
    o.z = fmaxf(fmaf(acc.z, inv, bv.z), 0.f);
    o.w = fmaxf(fmaf(acc.w, inv, bv.w), 0.f);
    ((float4*)(out + (size_t)warp * NODE_D))[lane] = o;
}

// ---------------------------------------------------------------------------
extern "C" void kernel_launch(void* const* d_in, const int* in_sizes, int n_in,
                              void* d_out, int out_size) {
    const float* x1  = (const float*)d_in[0];
    const void*  ei1 = d_in[1];
    const float* x2  = (const float*)d_in[3];
    const void*  ei2 = d_in[4];
    const float* W1  = (const float*)d_in[6];
    const float* as1 = (const float*)d_in[7];
    const float* ad1 = (const float*)d_in[8];
    const float* b1  = (const float*)d_in[9];
    const float* W2  = (const float*)d_in[10];
    const float* as2 = (const float*)d_in[11];
    const float* ad2 = (const float*)d_in[12];
    const float* b2  = (const float*)d_in[13];

    int N = in_sizes[0] / NODE_D;
    int E = in_sizes[1] / 2;
    int nb = (N + SCAN_B - 1) / SCAN_B;

    float* out = (float*)d_out;

    // idempotent, deterministic, capture-safe (not a stream/alloc API)
    cudaFuncSetAttribute(gemm_kernel,
                         cudaFuncAttributeMaxDynamicSharedMemorySize, SMEM_BYTES);

    dim3 zero_grid((N + 1023) / 1024, 2);
    dim3 conv_grid((2 * E + 255) / 256, 2);
    dim3 gemm_grid((N + 127) / 128, 2);
    dim3 scan_grid(nb, 2);
    dim3 one_grid(1, 2);
    dim3 scat_grid((E + 255) / 256, 2);
    dim3 gat_grid((N + 7) / 8, 2);          // 8 warps / block

    probe_kernel<<<1, 2>>>((const unsigned int*)ei1, (const unsigned int*)ei2);
    zero_kernel<<<zero_grid, 1024>>>(N);
    convert_hist_kernel<<<conv_grid, 256>>>(ei1, ei2, E);
    gemm_kernel<<<gemm_grid, 256, SMEM_BYTES>>>(x1, W1, as1, ad1, x2, W2, as2, ad2, N);
    scanA_kernel<<<scan_grid, SCAN_B>>>(N);
    scanB_kernel<<<one_grid, 64>>>(nb);
    scanC_kernel<<<scan_grid, SCAN_B>>>(N);
    scatter_kernel<<<scat_grid, 256>>>(E);
    gat_kernel<<<gat_grid, 256>>>(out, b1, b2, N);
}

// round 9
// speedup vs baseline: 3.0036x; 1.0820x over previous
#include <cuda_runtime.h>
#include <cuda_fp16.h>
#include <cuda_bf16.h>

#define NODE_D 128
#define NMAX   50048
#define EMAX   600064
#define SCAN_B 1024
#define GBK    64
#define XPAD   8

// dynamic smem layout (in __half units)
#define XS_W   (GBK + XPAD)       // 72
#define WS_W   (128 + XPAD)       // 136
#define OFF_XHI 0
#define OFF_XLO (128 * XS_W)
#define OFF_WHI (2 * 128 * XS_W)
#define OFF_WLO (2 * 128 * XS_W + GBK * WS_W)
#define SMEM_HALVES (2 * 128 * XS_W + 2 * GBK * WS_W)
#define SMEM_BYTES  (SMEM_HALVES * 2)

// Scratch (device globals: no allocations allowed)
__device__ float g_h[2][NMAX * NODE_D];   // projected features
__device__ float g_s[2][NMAX];            // h . a_src
__device__ float g_t[2][NMAX];            // h . a_dst
__device__ int   g_deg[2][NMAX];          // in-degree (excl self loop)
__device__ int   g_start[2][NMAX];        // CSR row start
__device__ int   g_cursor[2][NMAX];       // scatter cursor
__device__ int   g_csr[2][EMAX];          // src ids grouped by dst
__device__ int   g_ei[2][2 * EMAX];       // int32 edge indices (converted)
__device__ int   g_is64[2];               // dtype probe result
__device__ int   g_bsum[2][64];           // scan block sums

__device__ __forceinline__ float leaky(float x) { return x > 0.f ? x : 0.2f * x; }

__device__ __forceinline__ void ldsm4(unsigned r[4], const void* p) {
    unsigned a = (unsigned)__cvta_generic_to_shared(p);
    asm volatile("ldmatrix.sync.aligned.m8n8.x4.shared.b16 {%0,%1,%2,%3},[%4];"
                 : "=r"(r[0]), "=r"(r[1]), "=r"(r[2]), "=r"(r[3]) : "r"(a));
}
__device__ __forceinline__ void ldsm4t(unsigned r[4], const void* p) {
    unsigned a = (unsigned)__cvta_generic_to_shared(p);
    asm volatile("ldmatrix.sync.aligned.m8n8.x4.trans.shared.b16 {%0,%1,%2,%3},[%4];"
                 : "=r"(r[0]), "=r"(r[1]), "=r"(r[2]), "=r"(r[3]) : "r"(a));
}
__device__ __forceinline__ void mma16816(float c[4], const unsigned a[4], const unsigned b0, const unsigned b1) {
    asm volatile("mma.sync.aligned.m16n8k16.row.col.f32.f16.f16.f32 "
                 "{%0,%1,%2,%3},{%4,%5,%6,%7},{%8,%9},{%0,%1,%2,%3};"
                 : "+f"(c[0]), "+f"(c[1]), "+f"(c[2]), "+f"(c[3])
                 : "r"(a[0]), "r"(a[1]), "r"(a[2]), "r"(a[3]), "r"(b0), "r"(b1));
}

// ---------------------------------------------------------------------------
// 0a) Probe both edge buffers: int64 (all hi-words zero) vs int32.
// ---------------------------------------------------------------------------
__global__ void probe_kernel(const unsigned int* __restrict__ b0,
                             const unsigned int* __restrict__ b1) {
    int g = threadIdx.x;
    if (g >= 2) return;
    const unsigned int* buf = g ? b1 : b0;
    int nz = 0;
#pragma unroll
    for (int i = 0; i < 32; i++) nz += (buf[2 * i + 1] != 0u);
    g_is64[g] = (nz == 0) ? 1 : 0;
}

// 0b) Zero degree counters (graph replays need this every call).
__global__ void zero_kernel(int N) {
    int g = blockIdx.y;
    int i = blockIdx.x * blockDim.x + threadIdx.x;
    if (i < N) g_deg[g][i] = 0;
}

// 0c) Convert edge indices to int32 + histogram dst degrees.
__global__ void convert_hist_kernel(const void* __restrict__ b0,
                                    const void* __restrict__ b1, int E) {
    int g = blockIdx.y;
    const void* buf = g ? b1 : b0;
    int i = blockIdx.x * blockDim.x + threadIdx.x;
    if (i >= 2 * E) return;
    int v;
    if (g_is64[g]) v = (int)((const long long*)buf)[i];
    else           v = ((const int*)buf)[i];
    g_ei[g][i] = v;
    if (i >= E) atomicAdd(&g_deg[g][v], 1);   // second half = dst
}

// ---------------------------------------------------------------------------
// 1) GEMM via fp16 split tensor-core MMA: h = x @ W (+ fused s,t dots).
//    acc = xh*Wh + xh*Wl + xl*Wh (fp32). BM=128, BN=128, BK=64; 8 warps,
//    warp tile 32x64. Dynamic smem; 2 blocks/SM. s,t combined via smem
//    (plain stores, no atomics -> no zero-init dependency).
// ---------------------------------------------------------------------------
__global__ __launch_bounds__(256, 2)
void gemm_kernel(const float* __restrict__ x0, const float* __restrict__ W0,
                 const float* __restrict__ as0, const float* __restrict__ ad0,
                 const float* __restrict__ x1, const float* __restrict__ W1,
                 const float* __restrict__ as1, const float* __restrict__ ad1,
                 int N) {
    extern __shared__ __half smem[];
    __half* xs_hi = smem + OFF_XHI;   // [128][XS_W]
    __half* xs_lo = smem + OFF_XLO;
    __half* ws_hi = smem + OFF_WHI;   // [GBK][WS_W]
    __half* ws_lo = smem + OFF_WLO;

    int g = blockIdx.y;
    const float* __restrict__ x = g ? x1 : x0;
    const float* __restrict__ W = g ? W1 : W0;
    const float* __restrict__ a_src = g ? as1 : as0;
    const float* __restrict__ a_dst = g ? ad1 : ad0;
    float* __restrict__ h = g_h[g];

    int tid = threadIdx.x;
    int lane = tid & 31;
    int wid = tid >> 5;
    int warpM = wid >> 1;              // 0..3
    int warpN = wid & 1;               // 0..1
    int row0 = blockIdx.x * 128;

    float acc[2][8][4];
#pragma unroll
    for (int mi = 0; mi < 2; mi++)
#pragma unroll
        for (int ni = 0; ni < 8; ni++)
#pragma unroll
            for (int q = 0; q < 4; q++) acc[mi][ni][q] = 0.f;

    for (int k0 = 0; k0 < NODE_D; k0 += GBK) {
        // stage x tile (128 x 64): 2048 float4, 8 per thread, split hi/lo
#pragma unroll
        for (int i = 0; i < 8; i++) {
            int idx = tid + i * 256;
            int r = idx >> 4, kq = idx & 15;
            int gr = row0 + r;
            float4 v = (gr < N) ? ((const float4*)x)[gr * (NODE_D / 4) + (k0 >> 2) + kq]
                                : make_float4(0.f, 0.f, 0.f, 0.f);
            float vv[4] = {v.x, v.y, v.z, v.w};
#pragma unroll
            for (int j = 0; j < 4; j++) {
                __half hi = __float2half_rn(vv[j]);
                xs_hi[r * XS_W + kq * 4 + j] = hi;
                xs_lo[r * XS_W + kq * 4 + j] = __float2half_rn(vv[j] - __half2float(hi));
            }
        }
        // stage W tile (64 x 128): 2048 float4, 8 per thread
#pragma unroll
        for (int i = 0; i < 8; i++) {
            int idx = tid + i * 256;
            int k = idx >> 5, c4 = idx & 31;
            float4 v = ((const float4*)W)[(k0 + k) * (NODE_D / 4) + c4];
            float vv[4] = {v.x, v.y, v.z, v.w};
#pragma unroll
            for (int j = 0; j < 4; j++) {
                __half hi = __float2half_rn(vv[j]);
                ws_hi[k * WS_W + c4 * 4 + j] = hi;
                ws_lo[k * WS_W + c4 * 4 + j] = __float2half_rn(vv[j] - __half2float(hi));
            }
        }
        __syncthreads();

#pragma unroll
        for (int ks = 0; ks < GBK / 16; ks++) {
            int kb = ks * 16;
            unsigned a_hi[2][4], a_lo[2][4];
#pragma unroll
            for (int mi = 0; mi < 2; mi++) {
                int ar = warpM * 32 + mi * 16 + (lane & 15);
                int ac = kb + (lane >> 4) * 8;
                ldsm4(a_hi[mi], &xs_hi[ar * XS_W + ac]);
                ldsm4(a_lo[mi], &xs_lo[ar * XS_W + ac]);
            }
            // only one B hi/lo fragment pair live at a time (keeps regs <= 128)
#pragma unroll
            for (int np = 0; np < 4; np++) {
                int br = kb + (lane & 15);
                int bc = warpN * 64 + np * 16 + (lane >> 4) * 8;
                unsigned bh[4], bl[4];
                ldsm4t(bh, &ws_hi[br * WS_W + bc]);
                ldsm4t(bl, &ws_lo[br * WS_W + bc]);
#pragma unroll
                for (int mi = 0; mi < 2; mi++) {
                    mma16816(acc[mi][np * 2 + 0], a_hi[mi], bh[0], bh[1]);
                    mma16816(acc[mi][np * 2 + 1], a_hi[mi], bh[2], bh[3]);
                    mma16816(acc[mi][np * 2 + 0], a_hi[mi], bl[0], bl[1]);
                    mma16816(acc[mi][np * 2 + 1], a_hi[mi], bl[2], bl[3]);
                    mma16816(acc[mi][np * 2 + 0], a_lo[mi], bh[0], bh[1]);
                    mma16816(acc[mi][np * 2 + 1], a_lo[mi], bh[2], bh[3]);
                }
            }
        }
        __syncthreads();
    }

    // epilogue: store h + fused s,t dot partials
    int groupId = lane >> 2, tid4 = lane & 3;
    float ps[4] = {0.f, 0.f, 0.f, 0.f};
    float pt[4] = {0.f, 0.f, 0.f, 0.f};
#pragma unroll
    for (int ni = 0; ni < 8; ni++) {
        int col = warpN * 64 + ni * 8 + tid4 * 2;
        float sa0 = __ldg(a_src + col), sa1 = __ldg(a_src + col + 1);
        float da0 = __ldg(a_dst + col), da1 = __ldg(a_dst + col + 1);
#pragma unroll
        for (int mi = 0; mi < 2; mi++) {
            int row = row0 + warpM * 32 + mi * 16 + groupId;
            float c0 = acc[mi][ni][0], c1 = acc[mi][ni][1];
            float c2 = acc[mi][ni][2], c3 = acc[mi][ni][3];
            if (row < N)     *(float2*)(h + (size_t)row * NODE_D + col) = make_float2(c0, c1);
            if (row + 8 < N) *(float2*)(h + (size_t)(row + 8) * NODE_D + col) = make_float2(c2, c3);
            ps[mi * 2 + 0] += c0 * sa0 + c1 * sa1;
            ps[mi * 2 + 1] += c2 * sa0 + c3 * sa1;
            pt[mi * 2 + 0] += c0 * da0 + c1 * da1;
            pt[mi * 2 + 1] += c2 * da0 + c3 * da1;
        }
    }
#pragma unroll
    for (int off = 1; off <= 2; off <<= 1) {
#pragma unroll
        for (int q = 0; q < 4; q++) {
            ps[q] += __shfl_xor_sync(0xffffffffu, ps[q], off);
            pt[q] += __shfl_xor_sync(0xffffffffu, pt[q], off);
        }
    }
    // combine the two warpN halves via smem (staging buffers are free now)
    float* red_s = (float*)smem;          // [128]
    float* red_t = red_s + 128;           // [128]
    if (tid4 == 0 && warpN == 0) {
#pragma unroll
        for (int mi = 0; mi < 2; mi++)
#pragma unroll
            for (int hf = 0; hf < 2; hf++) {
                int rl = warpM * 32 + mi * 16 + hf * 8 + groupId;
                red_s[rl] = ps[mi * 2 + hf];
                red_t[rl] = pt[mi * 2 + hf];
            }
    }
    __syncthreads();
    if (tid4 == 0 && warpN == 1) {
#pragma unroll
        for (int mi = 0; mi < 2; mi++)
#pragma unroll
            for (int hf = 0; hf < 2; hf++) {
                int rl = warpM * 32 + mi * 16 + hf * 8 + groupId;
                int row = row0 + rl;
                if (row < N) {
                    g_s[g][row] = red_s[rl] + ps[mi * 2 + hf];
                    g_t[g][row] = red_t[rl] + pt[mi * 2 + hf];
                }
            }
    }
}

// ---------------------------------------------------------------------------
// 2) Exclusive scan of degrees (3 stages)
// ---------------------------------------------------------------------------
__global__ void scanA_kernel(int N) {
    int g = blockIdx.y;
    __shared__ int sh[SCAN_B];
    int t = threadIdx.x;
    int i = blockIdx.x * SCAN_B + t;
    int v = (i < N) ? g_deg[g][i] : 0;
    sh[t] = v;
    __syncthreads();
#pragma unroll
    for (int off = 1; off < SCAN_B; off <<= 1) {
        int u = (t >= off) ? sh[t - off] : 0;
        __syncthreads();
        sh[t] += u;
        __syncthreads();
    }
    if (i < N) g_start[g][i] = sh[t] - v;        // exclusive
    if (t == SCAN_B - 1) g_bsum[g][blockIdx.x] = sh[t];
}

__global__ void scanB_kernel(int nb) {
    int g = blockIdx.y;
    __shared__ int sh[64];
    int t = threadIdx.x;
    int v = (t < nb) ? g_bsum[g][t] : 0;
    sh[t] = v;
    __syncthreads();
#pragma unroll
    for (int off = 1; off < 64; off <<= 1) {
        int u = (t >= off) ? sh[t - off] : 0;
        __syncthreads();
        sh[t] += u;
        __syncthreads();
    }
    if (t < nb) g_bsum[g][t] = sh[t] - v;        // exclusive
}

__global__ void scanC_kernel(int N) {
    int g = blockIdx.y;
    int i = blockIdx.x * SCAN_B + threadIdx.x;
    if (i >= N) return;
    int s = g_start[g][i] + g_bsum[g][blockIdx.x];
    g_start[g][i] = s;
    g_cursor[g][i] = s;
}

// ---------------------------------------------------------------------------
// 3) Scatter src ids into CSR by dst.
// ---------------------------------------------------------------------------
__global__ void scatter_kernel(int E) {
    int g = blockIdx.y;
    int e = blockIdx.x * blockDim.x + threadIdx.x;
    if (e >= E) return;
    int src = g_ei[g][e];
    int dst = g_ei[g][E + e];
    int slot = atomicAdd(&g_cursor[g][dst], 1);
    g_csr[g][slot] = src;
}

// ---------------------------------------------------------------------------
// 4) Fused GAT: one warp per dst node. max -> exp-sum+gather-acc -> finalize.
// ---------------------------------------------------------------------------
__global__ __launch_bounds__(256)
void gat_kernel(float* __restrict__ out_base,
                const float* __restrict__ b0, const float* __restrict__ b1,
                int N) {
    int g = blockIdx.y;
    int warp = (blockIdx.x * blockDim.x + threadIdx.x) >> 5;
    int lane = threadIdx.x & 31;
    if (warp >= N) return;
    const float* bias = g ? b1 : b0;
    float* out = out_base + (size_t)g * N * NODE_D;
    const float* __restrict__ s_arr = g_s[g];
    const int* __restrict__ csr = g_csr[g];

    int start = g_start[g][warp];
    int deg = g_deg[g][warp];
    float tn = g_t[g][warp];
    float eself = leaky(s_arr[warp] + tn);

    // segment max (incl self loop)
    float m = eself;
    for (int i = lane; i < deg; i += 32) {
        int src = csr[start + i];
        m = fmaxf(m, leaky(s_arr[src] + tn));
    }
#pragma unroll
    for (int o = 16; o > 0; o >>= 1)
        m = fmaxf(m, __shfl_xor_sync(0xffffffffu, m, o));

    // accumulate: self first
    float den = __expf(eself - m);
    float4 hn = ((const float4*)(g_h[g] + (size_t)warp * NODE_D))[lane];
    float4 acc = make_float4(den * hn.x, den * hn.y, den * hn.z, den * hn.w);

    for (int i = 0; i < deg; i++) {
        int src = csr[start + i];
        float ex = __expf(leaky(s_arr[src] + tn) - m);
        float4 hv = ((const float4*)(g_h[g] + (size_t)src * NODE_D))[lane];
        acc.x = fmaf(ex, hv.x, acc.x);
        acc.y = fmaf(ex, hv.y, acc.y);
        acc.z = fmaf(ex, hv.z, acc.z);
        acc.w = fmaf(ex, hv.w, acc.w);
        den += ex;
    }

    float inv = 1.f / (den + 1e-16f);
    float4 bv = ((const float4*)bias)[lane];
    float4 o;
    o.x = fmaxf(fmaf(acc.x, inv, bv.x), 0.f);
    o.y = fmaxf(fmaf(acc.y, inv, bv.y), 0.f);
    o.z = fmaxf(fmaf(acc.z, inv, bv.z), 0.f);
    o.w = fmaxf(fmaf(acc.w, inv, bv.w), 0.f);
    ((float4*)(out + (size_t)warp * NODE_D))[lane] = o;
}

// ---------------------------------------------------------------------------
extern "C" void kernel_launch(void* const* d_in, const int* in_sizes, int n_in,
                              void* d_out, int out_size) {
    const float* x1  = (const float*)d_in[0];
    const void*  ei1 = d_in[1];
    const float* x2  = (const float*)d_in[3];
    const void*  ei2 = d_in[4];
    const float* W1  = (const float*)d_in[6];
    const float* as1 = (const float*)d_in[7];
    const float* ad1 = (const float*)d_in[8];
    const float* b1  = (const float*)d_in[9];
    const float* W2  = (const float*)d_in[10];
    const float* as2 = (const float*)d_in[11];
    const float* ad2 = (const float*)d_in[12];
    const float* b2  = (const float*)d_in[13];

    int N = in_sizes[0] / NODE_D;
    int E = in_sizes[1] / 2;
    int nb = (N + SCAN_B - 1) / SCAN_B;

    float* out = (float*)d_out;

    // idempotent, deterministic, capture-safe (not a stream/alloc API)
    cudaFuncSetAttribute(gemm_kernel,
                         cudaFuncAttributeMaxDynamicSharedMemorySize, SMEM_BYTES);

    dim3 zero_grid((N + 1023) / 1024, 2);
    dim3 conv_grid((2 * E + 255) / 256, 2);
    dim3 gemm_grid((N + 127) / 128, 2);
    dim3 scan_grid(nb, 2);
    dim3 one_grid(1, 2);
    dim3 scat_grid((E + 255) / 256, 2);
    dim3 gat_grid((N + 7) / 8, 2);          // 8 warps / block

    // fork a side stream so the CSR build overlaps the GEMM in the graph
    cudaStream_t s2;
    cudaEvent_t ev_fork, ev_join;
    cudaStreamCreateWithFlags(&s2, cudaStreamNonBlocking);
    cudaEventCreateWithFlags(&ev_fork, cudaEventDisableTiming);
    cudaEventCreateWithFlags(&ev_join, cudaEventDisableTiming);

    probe_kernel<<<1, 2>>>((const unsigned int*)ei1, (const unsigned int*)ei2);
    cudaEventRecord(ev_fork, 0);
    cudaStreamWaitEvent(s2, ev_fork, 0);

    // branch A (main stream): GEMM + fused dots
    gemm_kernel<<<gemm_grid, 256, SMEM_BYTES>>>(x1, W1, as1, ad1, x2, W2, as2, ad2, N);

    // branch B (side stream): CSR build
    zero_kernel<<<zero_grid, 1024, 0, s2>>>(N);
    convert_hist_kernel<<<conv_grid, 256, 0, s2>>>(ei1, ei2, E);
    scanA_kernel<<<scan_grid, SCAN_B, 0, s2>>>(N);
    scanB_kernel<<<one_grid, 64, 0, s2>>>(nb);
    scanC_kernel<<<scan_grid, SCAN_B, 0, s2>>>(N);
    scatter_kernel<<<scat_grid, 256, 0, s2>>>(E);
    cudaEventRecord(ev_join, s2);
    cudaStreamWaitEvent(0, ev_join, 0);

    // join: fused GAT aggregation
    gat_kernel<<<gat_grid, 256>>>(out, b1, b2, N);
}